// round 17
// baseline (speedup 1.0000x reference)
#include <cuda_runtime.h>
#include <cuda_fp16.h>
#include <cstdint>

// SuperchargingBKT — round 16: R15 with the cross-warp combine order fixed.
//
// R15 failed correctness: earlier-warp totals were multiplied ascending
// (E*T0*T1*T2) instead of descending (E*T2*T1*T0); 2x2 transition matrices
// don't commute. Only change: the combine loop now descends.
//
// Design (R15): persistent 1024-thread CTAs, (omega,sigma) half2 table
// (200KB) + kc float4 table (16KB) in smem, SEG=4, 4 warps/row combined via
// named barriers (bar.sync r+1, 128) with double-buffered row totals.
//
// Inputs (metadata order):
//  0 pL0_logit [K] f32   4 pS_logit [K] f32    8 observations [B,T] i32
//  1 pT_logit  [K] f32   5 omega    [P] f32    9 kc_ids       [B,T] i32
//  2 pF_logit  [K] f32   6 sigma    [P] f32   10 problem_ids  [B,T] i32
//  3 pG_logit  [K] f32   7 ability  [S,4] f32 11 student_ids  [B,T] i32
// Output: p_correct [B,T] f32

constexpr int T_LEN = 512;
constexpr int SEG   = 4;                   // steps per lane
constexpr int WPR   = 4;                   // warps per row (4*32*4 = 512)
constexpr int THREADS = 1024;              // 32 warps
constexpr int ROWS_PER_ITER = (THREADS / 32) / WPR;   // 8
constexpr int K_CAP = 1000;
constexpr int P_CAP = 50048;

constexpr int SMEM_PS  = P_CAP * 4;                    // 200192 B (__half2)
constexpr int SMEM_KC  = K_CAP * 16;                   // 16000 B (float4)
constexpr int SMEM_RT  = 2 * ROWS_PER_ITER * WPR * 16; // 1024 B (row totals x2)
constexpr int SMEM_TOTAL = SMEM_PS + SMEM_KC + SMEM_RT;  // 217216 B

// single-MUFU sigmoid: sigma(x) = 0.5*tanh(0.5x) + 0.5
__device__ __forceinline__ float sigmoidf(float x) {
    float t;
    asm("tanh.approx.f32 %0, %1;" : "=f"(t) : "f"(x * 0.5f));
    return fmaf(t, 0.5f, 0.5f);
}

__device__ __forceinline__ void bar_row(int id) {
    asm volatile("bar.sync %0, %1;" :: "r"(id), "r"(128) : "memory");
}

__global__ void __launch_bounds__(THREADS, 1)
bkt_scan(
    const float* __restrict__ pL0_logit,
    const float* __restrict__ pT_logit,
    const float* __restrict__ pF_logit,
    const float* __restrict__ pG_logit,
    const float* __restrict__ pS_logit,
    const float* __restrict__ omega,
    const float* __restrict__ sigma,
    const float4* __restrict__ ability,
    const int*  __restrict__ obs,
    const int*  __restrict__ kc,
    const int*  __restrict__ pid,
    const int*  __restrict__ sid,
    float* __restrict__ out,
    int B, int K, int P)
{
    extern __shared__ char smem[];
    __half2* psTab  = reinterpret_cast<__half2*>(smem);
    float4*  kcTab  = reinterpret_cast<float4*>(smem + SMEM_PS);
    float4*  rowTot = reinterpret_cast<float4*>(smem + SMEM_PS + SMEM_KC);

    const int tid  = threadIdx.x;
    const int lane = tid & 31;
    const int wid  = tid >> 5;               // 0..31
    const int r    = wid >> 2;               // row-in-iter 0..7
    const int w    = wid & 3;                // warp-in-row 0..3

    // ---- stage tables once (persistent) ----------------------------------
    for (int i = tid; i < P; i += THREADS)
        psTab[i] = __floats2half2_rn(omega[i], sigma[i]);
    for (int i = tid; i < K; i += THREADS)
        kcTab[i] = make_float4(pT_logit[i], pF_logit[i], pG_logit[i], pS_logit[i]);
    __syncthreads();

    const int numRB = B / ROWS_PER_ITER;     // 1024 row-blocks of 8 rows
    int it = 0;
    for (int rb = blockIdx.x; rb < numRB; rb += gridDim.x, ++it) {
        const int row  = rb * ROWS_PER_ITER + r;
        const int base = row * T_LEN;
        const int s0   = base + w * (32 * SEG) + lane * SEG;

        // ---- coalesced idx loads (16B lane stride) ------------------------
        int4 kv = *reinterpret_cast<const int4*>(kc  + s0);
        int4 pv = *reinterpret_cast<const int4*>(pid + s0);
        int4 sv = *reinterpret_cast<const int4*>(sid + s0);
        int4 ov = *reinterpret_cast<const int4*>(obs + s0);
        int kk[SEG] = {kv.x, kv.y, kv.z, kv.w};
        unsigned obits = (ov.x != 0 ? 1u : 0u) | (ov.y != 0 ? 2u : 0u)
                       | (ov.z != 0 ? 4u : 0u) | (ov.w != 0 ? 8u : 0u);

        // ---- front-load gathers: ability LDG (long-latency), ps LDS -------
        float4 th[SEG];
        th[0] = __ldg(ability + sv.x);
        th[1] = __ldg(ability + sv.y);
        th[2] = __ldg(ability + sv.z);
        th[3] = __ldg(ability + sv.w);
        __half2 ph[SEG];
        ph[0] = psTab[pv.x]; ph[1] = psTab[pv.y];
        ph[2] = psTab[pv.z]; ph[3] = psTab[pv.w];

        float pL0 = sigmoidf(__ldg(pL0_logit + __ldg(kc + base)));

        // ---- pass 1: coefficients + segment matrix product ----------------
        float C1[SEG], C2[SEG], C3[SEG], C4[SEG];
        float a00 = 1.f, a01 = 0.f, a10 = 0.f, a11 = 1.f;
#pragma unroll
        for (int i = 0; i < SEG; ++i) {
            float4 kcp = kcTab[kk[i]];               // LDS.128
            float2 psp = __half22float2(ph[i]);      // from LDS.32
            float pT = sigmoidf(kcp.x + th[i].x);
            float pF = sigmoidf(kcp.y - th[i].y);
            float pG = sigmoidf(kcp.z + psp.x + th[i].z);
            float pS = sigmoidf(kcp.w + psp.y - th[i].w);
            bool o = (obits >> i) & 1u;
            float pom = o ? (1.0f - pS) : pS;        // P(y | mastered)
            float pou = o ? pG : (1.0f - pG);        // P(y | unmastered)
            float c1 = (1.0f - pF) * pom;
            float c2 = pT * pou;
            float c3 = pF * pom;
            float c4 = (1.0f - pT) * pou;
            C1[i] = c1; C2[i] = c2; C3[i] = c3; C4[i] = c4;

            // A = M * A,  M = [[c4,c3],[c2,c1]]
            float n00 = fmaf(c4, a00, c3 * a10);
            float n01 = fmaf(c4, a01, c3 * a11);
            float n10 = fmaf(c2, a00, c1 * a10);
            float n11 = fmaf(c2, a01, c1 * a11);
            a00 = n00; a01 = n01; a10 = n10; a11 = n11;
        }
        {   // one normalization per 4-step segment
            float rn = __fdividef(1.0f, a00 + a01 + a10 + a11);
            a00 *= rn; a01 *= rn; a10 *= rn; a11 *= rn;
        }

        // ---- inclusive warp scan of segment matrices ----------------------
#pragma unroll
        for (int d = 1; d < 32; d <<= 1) {
            float b00 = __shfl_up_sync(0xFFFFFFFFu, a00, d);
            float b01 = __shfl_up_sync(0xFFFFFFFFu, a01, d);
            float b10 = __shfl_up_sync(0xFFFFFFFFu, a10, d);
            float b11 = __shfl_up_sync(0xFFFFFFFFu, a11, d);
            if (lane >= d) {
                float n00 = fmaf(a00, b00, a01 * b10);  // later * earlier
                float n01 = fmaf(a00, b01, a01 * b11);
                float n10 = fmaf(a10, b00, a11 * b10);
                float n11 = fmaf(a10, b01, a11 * b11);
                float rn = __fdividef(1.0f, n00 + n01 + n10 + n11);
                a00 = n00 * rn; a01 = n01 * rn; a10 = n10 * rn; a11 = n11 * rn;
            }
        }

        // publish this warp's total (lane 31 inclusive) to double buffer
        float4* rt = rowTot + ((it & 1) * ROWS_PER_ITER + r) * WPR;
        if (lane == 31) rt[w] = make_float4(a00, a01, a10, a11);

        // exclusive prefix within this warp
        float e00 = __shfl_up_sync(0xFFFFFFFFu, a00, 1);
        float e01 = __shfl_up_sync(0xFFFFFFFFu, a01, 1);
        float e10 = __shfl_up_sync(0xFFFFFFFFu, a10, 1);
        float e11 = __shfl_up_sync(0xFFFFFFFFu, a11, 1);
        if (lane == 0) { e00 = 1.f; e01 = 0.f; e10 = 0.f; e11 = 1.f; }

        bar_row(r + 1);     // totals of all 4 warps of this row visible

        // multiply in totals of earlier warps, DESCENDING:
        // e_full = E * T_{w-1} * T_{w-2} * ... * T_0   (later on the left)
        for (int k = w - 1; k >= 0; --k) {
            float4 t = rt[k];
            float n00 = fmaf(e00, t.x, e01 * t.z);
            float n01 = fmaf(e00, t.y, e01 * t.w);
            float n10 = fmaf(e10, t.x, e11 * t.z);
            float n11 = fmaf(e10, t.y, e11 * t.w);
            e00 = n00; e01 = n01; e10 = n10; e11 = n11;
        }

        // state at this lane's segment start
        float hu0 = 1.0f - pL0;
        float hm0 = pL0;
        float hu = fmaf(e00, hu0, e01 * hm0);
        float hm = fmaf(e10, hu0, e11 * hm0);
        float rs = __fdividef(1.0f, hu + hm);
        hu *= rs; hm *= rs;

        // ---- pass 2: replay segment, emit p_correct -----------------------
        float4 res;
        float* r4 = reinterpret_cast<float*>(&res);
#pragma unroll
        for (int i = 0; i < SEG; ++i) {
            float nm = fmaf(C1[i], hm, C2[i] * hu);
            float nu = fmaf(C3[i], hm, C4[i] * hu);
            float rn = __fdividef(1.0f, nm + nu);
            hm = nm * rn;
            hu = nu * rn;
            bool o = (obits >> i) & 1u;
            float pom = C1[i] + C3[i];             // = 1-pS if o else pS
            float pou = C2[i] + C4[i];             // = pG   if o else 1-pG
            float c5 = o ? pom : (1.0f - pom);     // 1-pS
            float c6 = o ? pou : (1.0f - pou);     // pG
            r4[i] = fmaf(c5, hm, c6 * hu);
        }
        *reinterpret_cast<float4*>(out + s0) = res;

        // reads of this iter's totals done before next iter's publish
        // (double buffer + this barrier make the overwrite safe)
        bar_row(r + 1);
    }
}

extern "C" void kernel_launch(void* const* d_in, const int* in_sizes, int n_in,
                              void* d_out, int out_size) {
    const float* pL0 = (const float*)d_in[0];
    const float* pT  = (const float*)d_in[1];
    const float* pF  = (const float*)d_in[2];
    const float* pG  = (const float*)d_in[3];
    const float* pS  = (const float*)d_in[4];
    const float* om  = (const float*)d_in[5];
    const float* sg  = (const float*)d_in[6];
    const float4* ab = (const float4*)d_in[7];
    const int* obs = (const int*)d_in[8];
    const int* kc  = (const int*)d_in[9];
    const int* pid = (const int*)d_in[10];
    const int* sid = (const int*)d_in[11];
    float* out = (float*)d_out;

    int K = in_sizes[0];                  // 1000
    int P = in_sizes[5];                  // 50000
    int B = in_sizes[8] / T_LEN;          // 8192 rows
    if (K > K_CAP) K = K_CAP;
    if (P > P_CAP) P = P_CAP;

    cudaFuncSetAttribute(bkt_scan,
                         cudaFuncAttributeMaxDynamicSharedMemorySize, SMEM_TOTAL);

    int numRB = B / ROWS_PER_ITER;        // 1024
    int grid = numRB < 148 ? numRB : 148;
    bkt_scan<<<grid, THREADS, SMEM_TOTAL>>>(pL0, pT, pF, pG, pS, om, sg, ab,
                                            obs, kc, pid, sid, out, B, K, P);
}